// round 10
// baseline (speedup 1.0000x reference)
#include <cuda_runtime.h>
#include <cstdint>

#define E_TOTAL   800000
#define D_IN      64
#define D_R       128
#define TILE_E    128
#define NTHREADS  512
#define GRID      148
#define NUM_TILES (E_TOTAL / TILE_E)  // 6250, exact
#define A_STRIDE  132                 // padded fp32 row stride (528B)
#define C_STRIDE  68                  // padded filt stride (272B)
#define GROUP_E   32                  // edges per 128-thread group
#define SCALE_FIX 1.000352f           // cancels tf32 truncation bias on A

struct Group {
    float A[2][GROUP_E * A_STRIDE];   // 2 x 16.9 KB (double-buffered)
    float filt[2][GROUP_E * C_STRIDE];// 2 k-half planes, 2 x 8.7 KB
};
struct Smem { Group gr[4]; };         // ~205 KB

// ---------------- helpers ----------------
__device__ __forceinline__ uint32_t smem_u32(const void* p) {
    uint32_t a;
    asm("{ .reg .u64 t; cvta.to.shared.u64 t, %1; cvt.u32.u64 %0, t; }" : "=r"(a) : "l"(p));
    return a;
}
__device__ __forceinline__ void cp_async16(uint32_t saddr, const void* gptr) {
    asm volatile("cp.async.cg.shared.global [%0], [%1], 16;" :: "r"(saddr), "l"(gptr));
}
#define CP_COMMIT() asm volatile("cp.async.commit_group;" ::: "memory")
#define CP_WAIT0()  asm volatile("cp.async.wait_group 0;" ::: "memory")
#define GBAR(id)    asm volatile("bar.sync %0, 128;" :: "r"(id) : "memory")

// ldmatrix x4 .b16 on an 8x8-f32-col-pair view: exact m16n8k8 tf32 A fragment.
__device__ __forceinline__ void ldsm_x4(uint32_t& r0, uint32_t& r1,
                                        uint32_t& r2, uint32_t& r3, uint32_t addr) {
    asm volatile("ldmatrix.sync.aligned.m8n8.x4.shared.b16 {%0,%1,%2,%3}, [%4];"
                 : "=r"(r0), "=r"(r1), "=r"(r2), "=r"(r3) : "r"(addr));
}

__device__ __forceinline__ void mma_tf32(float c[4],
                                         uint32_t a0, uint32_t a1, uint32_t a2, uint32_t a3,
                                         uint32_t b0, uint32_t b1) {
    asm volatile(
        "mma.sync.aligned.m16n8k8.row.col.f32.tf32.tf32.f32 "
        "{%0,%1,%2,%3}, {%4,%5,%6,%7}, {%8,%9}, {%0,%1,%2,%3};"
        : "+f"(c[0]), "+f"(c[1]), "+f"(c[2]), "+f"(c[3])
        : "r"(a0), "r"(a1), "r"(a2), "r"(a3), "r"(b0), "r"(b1));
}
__device__ __forceinline__ uint32_t f2tf32_rna(float f) {
    uint32_t r;
    asm("cvt.rna.tf32.f32 %0, %1;" : "=r"(r) : "f"(f));
    return r;
}
__device__ __forceinline__ void red_add_v4(float* p, float a, float b, float c, float d) {
    asm volatile("red.global.add.v4.f32 [%0], {%1, %2, %3, %4};"
                 :: "l"(p), "f"(a), "f"(b), "f"(c), "f"(d) : "memory");
}

__global__ void zero_out_kernel(float4* out, int n4) {
    int i = blockIdx.x * blockDim.x + threadIdx.x;
    if (i < n4) out[i] = make_float4(0.f, 0.f, 0.f, 0.f);
}

// Group loads its own 32 rows of tile tl: exactly 8 float4s per thread.
__device__ __forceinline__ void issue_group_tile(float* abuf, int tl, int grp, int tid_g,
                                                 const float* __restrict__ eb) {
    const float4* gp = reinterpret_cast<const float4*>(
        eb + ((size_t)tl * TILE_E + grp * GROUP_E) * D_R);
    #pragma unroll
    for (int q = 0; q < 8; q++) {
        int idx = q * 128 + tid_g;          // 0..1023
        int r   = idx >> 5;                 // local row 0..31
        int c4  = idx & 31;
        cp_async16(smem_u32(abuf + r * A_STRIDE + c4 * 4), gp + idx);
    }
}

// ---------------- main fused kernel ----------------
__global__ void __launch_bounds__(NTHREADS, 1)
fused_tf32_ksplit(const float* __restrict__ x,
                  const float* __restrict__ eb,
                  const int*   __restrict__ src,
                  const int*   __restrict__ dst,
                  const float* __restrict__ W,
                  const float* __restrict__ bias,
                  float*       __restrict__ out)
{
    extern __shared__ char smem_raw[];
    Smem* s = reinterpret_cast<Smem*>(smem_raw);

    const int tid   = threadIdx.x;
    const int lane  = tid & 31;
    const int g     = lane >> 2;      // 0..7
    const int t     = lane & 3;       // 0..3
    const int grp   = tid >> 7;       // 0..3
    const int tid_g = tid & 127;
    const int wig   = (tid >> 5) & 3; // warp-in-group
    const int kh    = wig & 1;        // k half (0: k<64, 1: k>=64)
    const int nh    = wig >> 1;       // n half (0: n<32, 1: n>=32)
    const int barid = 1 + grp;

    Group* G = &s->gr[grp];

    // ldmatrix per-lane offset (bytes) within an A buffer
    const int lrow = ((lane >> 3) & 1) * 8 + (lane & 7);
    const uint32_t laneoff = (uint32_t)(lrow * (A_STRIDE * 4) + (lane >> 4) * 16);
    const uint32_t abuf_addr[2] = { smem_u32(G->A[0]), smem_u32(G->A[1]) };

    // ---- W fragments in registers: 8 k-steps (this warp's k-half) x 4 n8-tiles ----
    // wreg[ks][j]: b0 = W[n][k], b1 = W[n][k+4]; n = nh*32 + j*8 + g, k = kh*64 + ks*8 + t
    float2 wreg[8][4];
    #pragma unroll
    for (int ks = 0; ks < 8; ks++) {
        #pragma unroll
        for (int j = 0; j < 4; j++) {
            int n = nh * 32 + j * 8 + g;
            int k = kh * 64 + ks * 8 + t;
            wreg[ks][j].x = __uint_as_float(f2tf32_rna(__ldg(W + n * D_R + k)));
            wreg[ks][j].y = __uint_as_float(f2tf32_rna(__ldg(W + n * D_R + k + 4)));
        }
    }
    const int d4 = tid_g & 15;
    const float4 bvec = __ldg(reinterpret_cast<const float4*>(bias) + d4);

    const int bid     = blockIdx.x;
    const int n_tiles = (NUM_TILES - bid + GRID - 1) / GRID;

    // ---- prologue: group prefetches its slice of tile 0 ----
    issue_group_tile(G->A[0], bid, grp, tid_g, eb);
    CP_COMMIT();

    for (int i = 0; i < n_tiles; i++) {
        CP_WAIT0();                 // this group's tile i slice resident
        GBAR(barid);                // publish A[i&1]; group finished iter i-1

        // ---- prefetch tile i+1 slice (overlaps MMA + epilogue below) ----
        if (i + 1 < n_tiles) {
            issue_group_tile(G->A[(i + 1) & 1], bid + (i + 1) * GRID, grp, tid_g, eb);
            CP_COMMIT();
        }

        const uint32_t abase = abuf_addr[i & 1] + laneoff + (uint32_t)(kh * 256);
        const int tl = bid + i * GRID;

        // ---- MMA: warp = 32 edges x 32 n x 64 k ----
        float c[2][4][4];
        #pragma unroll
        for (int m = 0; m < 2; m++)
            #pragma unroll
            for (int j = 0; j < 4; j++)
                { c[m][j][0] = 0.f; c[m][j][1] = 0.f; c[m][j][2] = 0.f; c[m][j][3] = 0.f; }

        #pragma unroll
        for (int ks = 0; ks < 8; ks++) {
            #pragma unroll
            for (int m = 0; m < 2; m++) {
                uint32_t a0, a1, a2, a3;
                ldsm_x4(a0, a1, a2, a3,
                        abase + (uint32_t)(m * 16 * (A_STRIDE * 4) + ks * 32));
                #pragma unroll
                for (int j = 0; j < 4; j++)
                    mma_tf32(c[m][j], a0, a1, a2, a3,
                             __float_as_uint(wreg[ks][j].x),
                             __float_as_uint(wreg[ks][j].y));
            }
        }

        // ---- stage C into this k-half's filt plane ----
        #pragma unroll
        for (int m = 0; m < 2; m++) {
            float* fr = G->filt[kh] + (m * 16 + g) * C_STRIDE + nh * 32;
            #pragma unroll
            for (int j = 0; j < 4; j++) {
                *reinterpret_cast<float2*>(fr + j * 8 + 2 * t) =
                    make_float2(c[m][j][0], c[m][j][1]);
                *reinterpret_cast<float2*>(fr + 8 * C_STRIDE + j * 8 + 2 * t) =
                    make_float2(c[m][j][2], c[m][j][3]);
            }
        }
        GBAR(barid);                // both filt planes complete

        // ---- scatter: combine k-half planes, 4 v4-chunks per thread ----
        const int ebase = tl * TILE_E + grp * GROUP_E;
        #pragma unroll
        for (int rep = 0; rep < 4; rep++) {
            int e_loc = (tid_g >> 4) + 8 * rep;   // 0..31
            const float* f0p = G->filt[0] + e_loc * C_STRIDE + d4 * 4;
            const float* f1p = G->filt[1] + e_loc * C_STRIDE + d4 * 4;
            float4 fa = *reinterpret_cast<const float4*>(f0p);
            float4 fb = *reinterpret_cast<const float4*>(f1p);
            int sn = __ldg(src + ebase + e_loc);
            int dn = __ldg(dst + ebase + e_loc);
            float4 xv = __ldg(reinterpret_cast<const float4*>(x + (size_t)sn * D_IN) + d4);
            red_add_v4(out + (size_t)dn * D_IN + d4 * 4,
                       fmaf(fa.x + fb.x, SCALE_FIX, bvec.x) * xv.x,
                       fmaf(fa.y + fb.y, SCALE_FIX, bvec.y) * xv.y,
                       fmaf(fa.z + fb.z, SCALE_FIX, bvec.z) * xv.z,
                       fmaf(fa.w + fb.w, SCALE_FIX, bvec.w) * xv.w);
        }
        // Next iteration's top GBAR (after CP_WAIT0) orders these filt reads
        // before the next staging writes; the A[(i+1)&1] overwrite was
        // ordered by this iteration's top GBAR.
    }
}

extern "C" void kernel_launch(void* const* d_in, const int* in_sizes, int n_in,
                              void* d_out, int out_size) {
    const float* x    = (const float*)d_in[0];
    const float* eb   = (const float*)d_in[1];
    const int*   src  = (const int*)d_in[2];
    const int*   dst  = (const int*)d_in[3];
    const float* W    = (const float*)d_in[4];
    const float* bias = (const float*)d_in[5];
    float* out = (float*)d_out;

    int n4 = out_size / 4;
    zero_out_kernel<<<(n4 + 255) / 256, 256>>>((float4*)out, n4);

    cudaFuncSetAttribute(fused_tf32_ksplit,
                         cudaFuncAttributeMaxDynamicSharedMemorySize,
                         (int)sizeof(Smem));
    fused_tf32_ksplit<<<GRID, NTHREADS, sizeof(Smem)>>>(x, eb, src, dst, W, bias, out);
}